// round 6
// baseline (speedup 1.0000x reference)
#include <cuda_runtime.h>

// ---------- f32x2 packed complex: one amp (re,im) per 64-bit reg ----------
typedef unsigned long long f2;

__device__ __forceinline__ f2 pk(float lo, float hi) {
    f2 r; asm("mov.b64 %0,{%1,%2};" : "=l"(r) : "f"(lo), "f"(hi)); return r;
}
__device__ __forceinline__ void upk(f2 v, float& lo, float& hi) {
    asm("mov.b64 {%0,%1},%2;" : "=f"(lo), "=f"(hi) : "l"(v));
}
__device__ __forceinline__ f2 add2(f2 a, f2 b) {
    f2 r; asm("add.rn.f32x2 %0,%1,%2;" : "=l"(r) : "l"(a), "l"(b)); return r;
}
__device__ __forceinline__ f2 mul2(f2 a, f2 b) {
    f2 r; asm("mul.rn.f32x2 %0,%1,%2;" : "=l"(r) : "l"(a), "l"(b)); return r;
}
__device__ __forceinline__ f2 fma2(f2 a, f2 b, f2 c) {
    f2 r; asm("fma.rn.f32x2 %0,%1,%2,%3;" : "=l"(r) : "l"(a), "l"(b), "l"(c)); return r;
}
__device__ __forceinline__ f2 swp(f2 v) {      // (lo,hi) -> (hi,lo)
    float lo, hi; upk(v, lo, hi); return pk(hi, lo);
}
__device__ __forceinline__ float fsqrt_ap(float x) {
    float r; asm("sqrt.approx.f32 %0, %1;" : "=f"(r) : "f"(x)); return r;
}
__device__ __forceinline__ float sx(float v, int m) {
    return __shfl_xor_sync(0xFFFFFFFFu, v, m, 32);
}

// Fused gate G_q = CNOT·CRX·(H⊗I) on local bits (LO=control, HI=target).
// H unnormalized (2^-12 folded into final prob scale).
// After butterflies u=a-b, v=e-d:  b_new = s*u + c*v, d_new = c*u + s*v, s = -i*sin.
// s*z packed: (sn*z.im, -sn*z.re) = snp (x) swp(z), snp = (sn,-sn).
template<int LO, int HI>
__device__ __forceinline__ void step_local(f2 (&Z)[16], f2 cp, f2 snp, f2 n1) {
    constexpr int L0 = 1 << LO, L1 = 1 << HI;
#pragma unroll
    for (int m = 0; m < 16; ++m) {
        if (m & (L0 | L1)) continue;
        const int a = m, b = m | L0, e = m | L1, d = m | L0 | L1;
        f2 u = fma2(n1, Z[b], Z[a]);     // a - b
        Z[a] = add2(Z[a], Z[b]);
        f2 v = fma2(n1, Z[d], Z[e]);     // e - d
        Z[e] = add2(Z[e], Z[d]);
        Z[b] = fma2(snp, swp(u), mul2(cp, v));   // s*u + c*v  (CNOT -> slot b)
        Z[d] = fma2(snp, swp(v), mul2(cp, u));   // c*u + s*v  (CNOT -> slot d)
    }
}

// Gate with control = local bit 3, target = lane bit M.
// CNOT case: new = s*self + c*partner.  FINAL (q=11, no CNOT): new = c*self + s*partner.
template<bool FINAL>
__device__ __forceinline__ void step_shfl(f2 (&Z)[16], f2 cp, f2 snp, f2 n1, int M) {
#pragma unroll
    for (int m = 0; m < 8; ++m) {        // H on local bit 3
        const int a = m, b = m | 8;
        f2 t = add2(Z[a], Z[b]);
        Z[b] = fma2(n1, Z[b], Z[a]);
        Z[a] = t;
    }
#pragma unroll
    for (int m = 8; m < 16; ++m) {       // CRX(+CNOT) across lane bit, control==1
        float sr, si; upk(Z[m], sr, si);
        float pr = sx(sr, M), pi = sx(si, M);
        if (FINAL) {
            Z[m] = fma2(cp, Z[m], mul2(snp, pk(pi, pr)));   // c*self + s*partner
        } else {
            Z[m] = fma2(snp, pk(si, sr), mul2(cp, pk(pr, pi)));  // s*self + c*partner
        }
    }
}

// conflict-free SMEM swizzle (8-byte elements)
__device__ __forceinline__ int sw(int i) { return i ^ ((i >> 4) & 31); }

// amp-index maps: thread t (0..255), local slot j (0..15)
#define AMPA(T,J) (((T) << 4) | (J))                                   // abs 0-3 local, bit4=lane0
#define AMPB(T,J) (((T) & 15) | ((J) << 4) | (((T) >> 4) << 8))        // abs 4-7 local, bit8=lane4
#define AMPC(T,J) (((T) & 255) | ((J) << 8))                           // abs 8-11 local, bit0=lane0

__global__ void __launch_bounds__(256, 4)
quantum_kernel(const float* __restrict__ x,
               const float* __restrict__ prm,
               float* __restrict__ out) {
    __shared__ f2 buf[4096];               // 32 KB transpose buffer
    __shared__ float2 cs[12];
    __shared__ float rsum[8], rcnt[8];
    __shared__ float s_ninv, s_sc;

    const int t = threadIdx.x, lane = t & 31, w = t >> 5;
    const float* __restrict__ xr = x + (size_t)blockIdx.x * 4096;

    // load 16 consecutive floats: abs index = t*16 + j (phase-A layout)
    float v[16];
#pragma unroll
    for (int k = 0; k < 4; ++k) {
        float4 q = *reinterpret_cast<const float4*>(xr + t * 16 + k * 4);
        v[4*k] = q.x; v[4*k+1] = q.y; v[4*k+2] = q.z; v[4*k+3] = q.w;
    }
    if (t < 12) { float th = prm[t] * 0.5f; cs[t] = make_float2(cosf(th), sinf(th)); }

    // row reduction: sum of squares + nonzero count
    float ss = 0.f, cn = 0.f;
#pragma unroll
    for (int j = 0; j < 16; ++j) {
        ss = fmaf(v[j], v[j], ss);
        cn += (v[j] != 0.f) ? 1.f : 0.f;
    }
#pragma unroll
    for (int m = 16; m >= 1; m >>= 1) {
        ss += sx(ss, m);
        cn += sx(cn, m);
    }
    if (lane == 0) { rsum[w] = ss; rcnt[w] = cn; }
    __syncthreads();
    if (t == 0) {
        float S = 0.f, C = 0.f;
#pragma unroll
        for (int k = 0; k < 8; ++k) { S += rsum[k]; C += rcnt[k]; }
        s_ninv = 1.f / (sqrtf(S) + 1e-8f);
        // 1/||q||^2 * (1/sqrt2)^24 from 12 folded Hadamards
        s_sc = (C > 0.f ? 1.f / C : 0.f) * (1.f / 4096.f);
    }
    __syncthreads();
    const float ninv = s_ninv;

    // _to_quantum: re = x*ninv (|.|<1 guaranteed); im = sgn * sqrt(1-re^2)
    f2 Z[16];
#pragma unroll
    for (int j = 0; j < 16; ++j) {
        float xv = v[j];
        float r  = xv * ninv;
        float g  = (xv > 0.f) ? 1.f : ((xv < 0.f) ? -1.f : 0.f);
        float im = g * fsqrt_ap(fmaxf(fmaf(-r, r, 1.f), 0.f));
        Z[j] = pk(r, im);
    }

    const f2 n1 = pk(-1.f, -1.f);

#define LSTEP(Q,LO,HI) { float2 g = cs[Q]; \
    step_local<LO,HI>(Z, pk(g.x, g.x), pk(g.y, -g.y), n1); }
#define SSTEP(Q,M,F)   { float2 g = cs[Q]; \
    step_shfl<F>(Z, pk(g.x, g.x), pk(g.y, -g.y), n1, M); }

#define XPOSE(AW, AR) { \
    _Pragma("unroll") for (int j = 0; j < 16; ++j) \
        buf[sw(AW(t, j))] = Z[j]; \
    __syncthreads(); \
    _Pragma("unroll") for (int j = 0; j < 16; ++j) \
        Z[j] = buf[sw(AR(t, j))]; \
    __syncthreads(); }

    // Phase A: q=0,1,2 local on abs (0,1),(1,2),(2,3); q=3 on (3,4): lane bit0
    LSTEP(0, 0, 1) LSTEP(1, 1, 2) LSTEP(2, 2, 3)
    SSTEP(3, 1, false)
    XPOSE(AMPA, AMPB)
    // Phase B: q=4,5,6 local on abs (4,5),(5,6),(6,7); q=7 on (7,8): lane bit4
    LSTEP(4, 0, 1) LSTEP(5, 1, 2) LSTEP(6, 2, 3)
    SSTEP(7, 16, false)
    XPOSE(AMPB, AMPC)
    // Phase C: q=8,9,10 local on abs (8,9),(9,10),(10,11); q=11 on (11,0): lane bit0, NO CNOT
    LSTEP(8, 0, 1) LSTEP(9, 1, 2) LSTEP(10, 2, 3)
    SSTEP(11, 1, true)

    // output: abs = (j<<8) | t — consecutive t per j => fully coalesced 128B/warp
    const float sc = s_sc;
    float* __restrict__ orow = out + (size_t)blockIdx.x * 4096;
#pragma unroll
    for (int j = 0; j < 16; ++j) {
        float r, im; upk(Z[j], r, im);
        orow[(j << 8) | t] = fmaf(r, r, im * im) * sc;
    }
}

extern "C" void kernel_launch(void* const* d_in, const int* in_sizes, int n_in,
                              void* d_out, int out_size) {
    const float* state  = (const float*)d_in[0];
    const float* params = (const float*)d_in[1];
    float* out = (float*)d_out;
    int rows = in_sizes[0] / 4096;   // 4096 rows
    quantum_kernel<<<rows, 256>>>(state, params, out);
}